// round 2
// baseline (speedup 1.0000x reference)
#include <cuda_runtime.h>
#include <cuda_fp16.h>
#include <cstdint>

#define NTOK 8192
#define DIM  1024

// ---------------- static device scratch (no runtime allocation) ----------------
__device__ __half g_xh[NTOK * DIM];             // x in fp16
__device__ __half g_wt[3 * DIM * DIM];          // Wq/Wk/Wv transposed: [dout][din]
__device__ __half g_qh[NTOK * DIM];             // Q fp16
__device__ __half g_kh[NTOK * DIM];             // K fp16
__device__ __half g_vh[NTOK * DIM];             // V fp16 (row-major)
__device__ __half g_vt[DIM * NTOK];             // V^T fp16: [d][n]
__device__ __half g_p[(size_t)NTOK * NTOK];     // unnormalized softmax numerator
__device__ float  g_rowsum[NTOK];               // softmax denominators

// ---------------- helpers ----------------
__device__ __forceinline__ unsigned sptr(const void* p) {
    return (unsigned)__cvta_generic_to_shared(p);
}
__device__ __forceinline__ void cp16(void* dst, const void* src) {
    asm volatile("cp.async.cg.shared.global [%0], [%1], 16;\n"
                 :: "r"(sptr(dst)), "l"(src));
}

// ---------------- shared GEMM core: C[M,N] = A[M,K] @ B[N,K]^T ----------------
// A, B fp16 row-major (K contiguous). CTA tile 128x128, K-step 32, 8 warps (4x2),
// warp tile 32x64, mma.sync.m16n8k16 with fp32 accumulation.
// Smem rows padded to 40 halves (80B stride -> 20-bank stride: 8-row LDSM groups
// hit banks {0,20,8,28,16,4,24,12}(+0..3) = all 32 banks -> conflict-free).
//
// EPI 0: store fp16 C (QKV)
// EPI 1: P = exp2(C*scale*log2e) fp16 + atomic fp32 row sums (scores+softmax-numer)
// EPI 2: C * (1/rowsum[row]) -> fp32 out (attention output)
template<int EPI>
__device__ __forceinline__ void gemm_core(const __half* __restrict__ A,
                                          const __half* __restrict__ B,
                                          __half* __restrict__ Ch,
                                          float* __restrict__ Cf,
                                          int K, int ldc)
{
    __shared__ __half sA[2][128 * 40];
    __shared__ __half sB[2][128 * 40];

    const int tid  = threadIdx.x;
    const int lane = tid & 31;
    const int warp = tid >> 5;
    const int wm   = (warp & 3) * 32;
    const int wn   = (warp >> 2) * 64;

    const long mBase = (long)blockIdx.y * 128;
    const long nBase = (long)blockIdx.x * 128;
    const __half* Ag = A + mBase * K;
    const __half* Bg = B + nBase * K;

    // loader mapping: 512 16B-chunks per tile, 2 per thread (rows r0, r0+64)
    const int r0 = tid >> 2;
    const int c8 = (tid & 3) * 8;

    float acc[2][8][4];
    #pragma unroll
    for (int i = 0; i < 2; i++)
        #pragma unroll
        for (int j = 0; j < 8; j++)
            #pragma unroll
            for (int q = 0; q < 4; q++) acc[i][j][q] = 0.f;

    const int KT = K >> 5;

    // prologue: stage 0
    {
        cp16(&sA[0][r0 * 40 + c8],        Ag + (long)r0 * K + c8);
        cp16(&sA[0][(r0 + 64) * 40 + c8], Ag + (long)(r0 + 64) * K + c8);
        cp16(&sB[0][r0 * 40 + c8],        Bg + (long)r0 * K + c8);
        cp16(&sB[0][(r0 + 64) * 40 + c8], Bg + (long)(r0 + 64) * K + c8);
        asm volatile("cp.async.commit_group;\n");
    }

    int buf = 0;
    for (int kt = 0; kt < KT; ++kt) {
        if (kt + 1 < KT) {
            const int nb = buf ^ 1;
            const long ko = (long)(kt + 1) * 32 + c8;
            cp16(&sA[nb][r0 * 40 + c8],        Ag + (long)r0 * K + ko);
            cp16(&sA[nb][(r0 + 64) * 40 + c8], Ag + (long)(r0 + 64) * K + ko);
            cp16(&sB[nb][r0 * 40 + c8],        Bg + (long)r0 * K + ko);
            cp16(&sB[nb][(r0 + 64) * 40 + c8], Bg + (long)(r0 + 64) * K + ko);
            asm volatile("cp.async.commit_group;\n");
            asm volatile("cp.async.wait_group 1;\n");
        } else {
            asm volatile("cp.async.wait_group 0;\n");
        }
        __syncthreads();

        const __half* a_s = sA[buf];
        const __half* b_s = sB[buf];
        #pragma unroll
        for (int kk = 0; kk < 2; ++kk) {
            unsigned af[2][4];
            unsigned bf[4][4];
            #pragma unroll
            for (int mi = 0; mi < 2; ++mi) {
                const int row = wm + mi * 16 + (lane & 15);
                const int col = kk * 16 + (lane >> 4) * 8;
                const unsigned addr = sptr(a_s + row * 40 + col);
                asm volatile("ldmatrix.sync.aligned.m8n8.x4.shared.b16 {%0,%1,%2,%3}, [%4];\n"
                             : "=r"(af[mi][0]), "=r"(af[mi][1]),
                               "=r"(af[mi][2]), "=r"(af[mi][3])
                             : "r"(addr));
            }
            #pragma unroll
            for (int nq = 0; nq < 4; ++nq) {
                const int g   = lane >> 3;
                const int row = wn + nq * 16 + (g >> 1) * 8 + (lane & 7);
                const int col = kk * 16 + (g & 1) * 8;
                const unsigned addr = sptr(b_s + row * 40 + col);
                asm volatile("ldmatrix.sync.aligned.m8n8.x4.shared.b16 {%0,%1,%2,%3}, [%4];\n"
                             : "=r"(bf[nq][0]), "=r"(bf[nq][1]),
                               "=r"(bf[nq][2]), "=r"(bf[nq][3])
                             : "r"(addr));
            }
            #pragma unroll
            for (int mi = 0; mi < 2; ++mi) {
                #pragma unroll
                for (int ni = 0; ni < 8; ++ni) {
                    const unsigned b0 = bf[ni >> 1][(ni & 1) * 2 + 0];
                    const unsigned b1 = bf[ni >> 1][(ni & 1) * 2 + 1];
                    asm volatile(
                        "mma.sync.aligned.m16n8k16.row.col.f32.f16.f16.f32 "
                        "{%0,%1,%2,%3},{%4,%5,%6,%7},{%8,%9},{%0,%1,%2,%3};\n"
                        : "+f"(acc[mi][ni][0]), "+f"(acc[mi][ni][1]),
                          "+f"(acc[mi][ni][2]), "+f"(acc[mi][ni][3])
                        : "r"(af[mi][0]), "r"(af[mi][1]),
                          "r"(af[mi][2]), "r"(af[mi][3]),
                          "r"(b0), "r"(b1));
                }
            }
        }
        __syncthreads();
        buf ^= 1;
    }

    // ---------------- epilogue ----------------
    const int qr = lane >> 2;
    const int qc = (lane & 3) * 2;

    if (EPI == 0) {
        #pragma unroll
        for (int mi = 0; mi < 2; ++mi) {
            const long row = mBase + wm + mi * 16 + qr;
            #pragma unroll
            for (int ni = 0; ni < 8; ++ni) {
                const long col = nBase + wn + ni * 8 + qc;
                *(__half2*)(Ch + row * ldc + col) =
                    __floats2half2_rn(acc[mi][ni][0], acc[mi][ni][1]);
                *(__half2*)(Ch + (row + 8) * ldc + col) =
                    __floats2half2_rn(acc[mi][ni][2], acc[mi][ni][3]);
            }
        }
    } else if (EPI == 1) {
        // exp(s / sqrt(1024)) = exp2(s * 0.03125 * log2(e)); |s*scale| <~ 3 so
        // no max subtraction needed (softmax is shift invariant, range is safe).
        const float SC = 0.03125f * 1.4426950408889634f;
        float rs[4] = {0.f, 0.f, 0.f, 0.f};
        #pragma unroll
        for (int mi = 0; mi < 2; ++mi) {
            const long row = mBase + wm + mi * 16 + qr;
            #pragma unroll
            for (int ni = 0; ni < 8; ++ni) {
                const long col = nBase + wn + ni * 8 + qc;
                const float p0 = exp2f(acc[mi][ni][0] * SC);
                const float p1 = exp2f(acc[mi][ni][1] * SC);
                const float p2 = exp2f(acc[mi][ni][2] * SC);
                const float p3 = exp2f(acc[mi][ni][3] * SC);
                const __half2 h0 = __floats2half2_rn(p0, p1);
                const __half2 h1 = __floats2half2_rn(p2, p3);
                *(__half2*)(Ch + row * ldc + col)       = h0;
                *(__half2*)(Ch + (row + 8) * ldc + col) = h1;
                // sum the rounded values so numerator/denominator stay consistent
                const float2 f0 = __half22float2(h0);
                const float2 f1 = __half22float2(h1);
                rs[mi * 2 + 0] += f0.x + f0.y;
                rs[mi * 2 + 1] += f1.x + f1.y;
            }
        }
        #pragma unroll
        for (int i = 0; i < 4; i++) {
            rs[i] += __shfl_xor_sync(0xffffffffu, rs[i], 1);
            rs[i] += __shfl_xor_sync(0xffffffffu, rs[i], 2);
        }
        if ((lane & 3) == 0) {
            #pragma unroll
            for (int mi = 0; mi < 2; ++mi) {
                const long row = mBase + wm + mi * 16 + qr;
                atomicAdd(&g_rowsum[row],     rs[mi * 2 + 0]);
                atomicAdd(&g_rowsum[row + 8], rs[mi * 2 + 1]);
            }
        }
    } else {
        #pragma unroll
        for (int mi = 0; mi < 2; ++mi) {
            const long row  = mBase + wm + mi * 16 + qr;
            const float inv0 = 1.0f / g_rowsum[row];
            const float inv1 = 1.0f / g_rowsum[row + 8];
            #pragma unroll
            for (int ni = 0; ni < 8; ++ni) {
                const long col = nBase + wn + ni * 8 + qc;
                const float2 o0 = make_float2(acc[mi][ni][0] * inv0,
                                              acc[mi][ni][1] * inv0);
                const float2 o1 = make_float2(acc[mi][ni][2] * inv1,
                                              acc[mi][ni][3] * inv1);
                *(float2*)(Cf + row * ldc + col)       = o0;
                *(float2*)(Cf + (row + 8) * ldc + col) = o1;
            }
        }
    }
}

// ---------------- prep kernels ----------------
// x fp32 -> fp16, and zero the rowsum accumulators (folded in: saves a launch)
__global__ void k_cvt_x(const float* __restrict__ x) {
    const long g = (long)blockIdx.x * blockDim.x + threadIdx.x;
    const long i = g * 4;
    const float4 v = *(const float4*)(x + i);
    *(__half2*)(g_xh + i)     = __floats2half2_rn(v.x, v.y);
    *(__half2*)(g_xh + i + 2) = __floats2half2_rn(v.z, v.w);
    if (g < NTOK) g_rowsum[g] = 0.f;
}

// W [din][dout] fp32 -> g_wt[z] [dout][din] fp16 (transpose + convert)
__global__ void k_cvt_w(const float* __restrict__ Wq,
                        const float* __restrict__ Wk,
                        const float* __restrict__ Wv) {
    const float* W = (blockIdx.z == 0) ? Wq : (blockIdx.z == 1) ? Wk : Wv;
    __half* out = g_wt + (size_t)blockIdx.z * DIM * DIM;
    __shared__ float t[32][33];
    const int x0 = blockIdx.x * 32, y0 = blockIdx.y * 32;
    for (int r = threadIdx.y; r < 32; r += 8)
        t[r][threadIdx.x] = W[(long)(y0 + r) * DIM + x0 + threadIdx.x];
    __syncthreads();
    for (int r = threadIdx.y; r < 32; r += 8)
        out[(long)(x0 + r) * DIM + y0 + threadIdx.x] =
            __float2half_rn(t[threadIdx.x][r]);
}

// g_vh [n][d] -> g_vt [d][n]
__global__ void k_transpose_v() {
    __shared__ __half t[32][33];
    const int x0 = blockIdx.x * 32;  // d
    const int y0 = blockIdx.y * 32;  // n
    for (int r = threadIdx.y; r < 32; r += 8)
        t[r][threadIdx.x] = g_vh[(long)(y0 + r) * DIM + x0 + threadIdx.x];
    __syncthreads();
    for (int r = threadIdx.y; r < 32; r += 8)
        g_vt[(long)(x0 + r) * NTOK + y0 + threadIdx.x] = t[threadIdx.x][r];
}

// ---------------- GEMM entry points ----------------
__global__ void k_gemm_qkv() {
    const __half* Bz = g_wt + (size_t)blockIdx.z * DIM * DIM;
    __half* Cz = (blockIdx.z == 0) ? g_qh : (blockIdx.z == 1) ? g_kh : g_vh;
    gemm_core<0>(g_xh, Bz, Cz, nullptr, DIM, DIM);
}
__global__ void k_gemm_s() {
    gemm_core<1>(g_qh, g_kh, g_p, nullptr, DIM, NTOK);
}
__global__ void k_gemm_o(float* __restrict__ out) {
    gemm_core<2>(g_p, g_vt, nullptr, out, NTOK, DIM);
}

// ---------------- launch ----------------
extern "C" void kernel_launch(void* const* d_in, const int* in_sizes, int n_in,
                              void* d_out, int out_size) {
    const float* x  = (const float*)d_in[0];
    const float* Wq = (const float*)d_in[1];
    const float* Wk = (const float*)d_in[2];
    const float* Wv = (const float*)d_in[3];
    float* out = (float*)d_out;

    k_cvt_x<<<(NTOK * DIM) / (256 * 4), 256>>>(x);
    k_cvt_w<<<dim3(32, 32, 3), dim3(32, 8)>>>(Wq, Wk, Wv);
    k_gemm_qkv<<<dim3(DIM / 128, NTOK / 128, 3), 256>>>();
    k_transpose_v<<<dim3(DIM / 32, NTOK / 32), dim3(32, 8)>>>();
    k_gemm_s<<<dim3(NTOK / 128, NTOK / 128), 256>>>();
    k_gemm_o<<<dim3(DIM / 128, NTOK / 128), 256>>>(out);
}

// round 8
// speedup vs baseline: 1.0432x; 1.0432x over previous
#include <cuda_runtime.h>
#include <cuda_fp16.h>
#include <cstdint>

#define NTOK 8192
#define DIM  1024

// ---------------- static device scratch (no runtime allocation) ----------------
__device__ __half g_xh[NTOK * DIM];             // x fp16 (also serves as K operand)
__device__ __half g_wq[DIM * DIM];              // Wq fp16 [din][dout]
__device__ __half g_wk[DIM * DIM];              // Wk fp16 [din][dout]
__device__ __half g_wvt[DIM * DIM];             // Wv^T fp16 [dout][din]
__device__ __half g_mt[DIM * DIM];              // g_mt[d][i] = sum_j Wk[d][j] Wq[i][j]
__device__ __half g_qp[NTOK * DIM];             // Q' = x @ (Wq Wk^T): [n][d]
__device__ __half g_vt[DIM * NTOK];             // V^T: [d][n]
__device__ __half g_p[(size_t)NTOK * NTOK];     // unnormalized softmax numerator
__device__ float  g_rowsum[NTOK];               // softmax denominators

// ---------------- helpers ----------------
__device__ __forceinline__ unsigned sptr(const void* p) {
    return (unsigned)__cvta_generic_to_shared(p);
}
__device__ __forceinline__ void cp16(void* dst, const void* src) {
    asm volatile("cp.async.cg.shared.global [%0], [%1], 16;\n"
                 :: "r"(sptr(dst)), "l"(src));
}

// ---------------- shared GEMM core: C[M,N] = A[M,K] @ B[N,K]^T ----------------
// (verbatim from the passing R2 kernel)
// A, B fp16 row-major (K contiguous). CTA tile 128x128, K-step 32, 8 warps (4x2),
// warp tile 32x64, mma.sync.m16n8k16 with fp32 accumulation.
// Smem rows padded to 40 halves (80B stride -> 20-bank stride: 8-row LDSM groups
// hit banks {0,20,8,28,16,4,24,12}(+0..3) = all 32 banks -> conflict-free).
//
// EPI 0: store fp16 C
// EPI 1: P = exp2(C*scale*log2e) fp16 + atomic fp32 row sums
// EPI 2: C * (1/rowsum[row]) -> fp32 out
template<int EPI>
__device__ __forceinline__ void gemm_core(const __half* __restrict__ A,
                                          const __half* __restrict__ B,
                                          __half* __restrict__ Ch,
                                          float* __restrict__ Cf,
                                          int K, int ldc)
{
    __shared__ __half sA[2][128 * 40];
    __shared__ __half sB[2][128 * 40];

    const int tid  = threadIdx.x;
    const int lane = tid & 31;
    const int warp = tid >> 5;
    const int wm   = (warp & 3) * 32;
    const int wn   = (warp >> 2) * 64;

    const long mBase = (long)blockIdx.y * 128;
    const long nBase = (long)blockIdx.x * 128;
    const __half* Ag = A + mBase * K;
    const __half* Bg = B + nBase * K;

    // loader mapping: 512 16B-chunks per tile, 2 per thread (rows r0, r0+64)
    const int r0 = tid >> 2;
    const int c8 = (tid & 3) * 8;

    float acc[2][8][4];
    #pragma unroll
    for (int i = 0; i < 2; i++)
        #pragma unroll
        for (int j = 0; j < 8; j++)
            #pragma unroll
            for (int q = 0; q < 4; q++) acc[i][j][q] = 0.f;

    const int KT = K >> 5;

    // prologue: stage 0
    {
        cp16(&sA[0][r0 * 40 + c8],        Ag + (long)r0 * K + c8);
        cp16(&sA[0][(r0 + 64) * 40 + c8], Ag + (long)(r0 + 64) * K + c8);
        cp16(&sB[0][r0 * 40 + c8],        Bg + (long)r0 * K + c8);
        cp16(&sB[0][(r0 + 64) * 40 + c8], Bg + (long)(r0 + 64) * K + c8);
        asm volatile("cp.async.commit_group;\n");
    }

    int buf = 0;
    for (int kt = 0; kt < KT; ++kt) {
        if (kt + 1 < KT) {
            const int nb = buf ^ 1;
            const long ko = (long)(kt + 1) * 32 + c8;
            cp16(&sA[nb][r0 * 40 + c8],        Ag + (long)r0 * K + ko);
            cp16(&sA[nb][(r0 + 64) * 40 + c8], Ag + (long)(r0 + 64) * K + ko);
            cp16(&sB[nb][r0 * 40 + c8],        Bg + (long)r0 * K + ko);
            cp16(&sB[nb][(r0 + 64) * 40 + c8], Bg + (long)(r0 + 64) * K + ko);
            asm volatile("cp.async.commit_group;\n");
            asm volatile("cp.async.wait_group 1;\n");
        } else {
            asm volatile("cp.async.wait_group 0;\n");
        }
        __syncthreads();

        const __half* a_s = sA[buf];
        const __half* b_s = sB[buf];
        #pragma unroll
        for (int kk = 0; kk < 2; ++kk) {
            unsigned af[2][4];
            unsigned bf[4][4];
            #pragma unroll
            for (int mi = 0; mi < 2; ++mi) {
                const int row = wm + mi * 16 + (lane & 15);
                const int col = kk * 16 + (lane >> 4) * 8;
                const unsigned addr = sptr(a_s + row * 40 + col);
                asm volatile("ldmatrix.sync.aligned.m8n8.x4.shared.b16 {%0,%1,%2,%3}, [%4];\n"
                             : "=r"(af[mi][0]), "=r"(af[mi][1]),
                               "=r"(af[mi][2]), "=r"(af[mi][3])
                             : "r"(addr));
            }
            #pragma unroll
            for (int nq = 0; nq < 4; ++nq) {
                const int g   = lane >> 3;
                const int row = wn + nq * 16 + (g >> 1) * 8 + (lane & 7);
                const int col = kk * 16 + (g & 1) * 8;
                const unsigned addr = sptr(b_s + row * 40 + col);
                asm volatile("ldmatrix.sync.aligned.m8n8.x4.shared.b16 {%0,%1,%2,%3}, [%4];\n"
                             : "=r"(bf[nq][0]), "=r"(bf[nq][1]),
                               "=r"(bf[nq][2]), "=r"(bf[nq][3])
                             : "r"(addr));
            }
            #pragma unroll
            for (int mi = 0; mi < 2; ++mi) {
                #pragma unroll
                for (int ni = 0; ni < 8; ++ni) {
                    const unsigned b0 = bf[ni >> 1][(ni & 1) * 2 + 0];
                    const unsigned b1 = bf[ni >> 1][(ni & 1) * 2 + 1];
                    asm volatile(
                        "mma.sync.aligned.m16n8k16.row.col.f32.f16.f16.f32 "
                        "{%0,%1,%2,%3},{%4,%5,%6,%7},{%8,%9},{%0,%1,%2,%3};\n"
                        : "+f"(acc[mi][ni][0]), "+f"(acc[mi][ni][1]),
                          "+f"(acc[mi][ni][2]), "+f"(acc[mi][ni][3])
                        : "r"(af[mi][0]), "r"(af[mi][1]),
                          "r"(af[mi][2]), "r"(af[mi][3]),
                          "r"(b0), "r"(b1));
                }
            }
        }
        __syncthreads();
        buf ^= 1;
    }

    // ---------------- epilogue ----------------
    const int qr = lane >> 2;
    const int qc = (lane & 3) * 2;

    if (EPI == 0) {
        #pragma unroll
        for (int mi = 0; mi < 2; ++mi) {
            const long row = mBase + wm + mi * 16 + qr;
            #pragma unroll
            for (int ni = 0; ni < 8; ++ni) {
                const long col = nBase + wn + ni * 8 + qc;
                *(__half2*)(Ch + row * ldc + col) =
                    __floats2half2_rn(acc[mi][ni][0], acc[mi][ni][1]);
                *(__half2*)(Ch + (row + 8) * ldc + col) =
                    __floats2half2_rn(acc[mi][ni][2], acc[mi][ni][3]);
            }
        }
    } else if (EPI == 1) {
        // exp(s / sqrt(1024)) = exp2(s * 0.03125 * log2(e)); |s*scale| <~ 3 so
        // no max subtraction needed (softmax is shift invariant, range is safe).
        const float SC = 0.03125f * 1.4426950408889634f;
        float rs[4] = {0.f, 0.f, 0.f, 0.f};
        #pragma unroll
        for (int mi = 0; mi < 2; ++mi) {
            const long row = mBase + wm + mi * 16 + qr;
            #pragma unroll
            for (int ni = 0; ni < 8; ++ni) {
                const long col = nBase + wn + ni * 8 + qc;
                const float p0 = exp2f(acc[mi][ni][0] * SC);
                const float p1 = exp2f(acc[mi][ni][1] * SC);
                const float p2 = exp2f(acc[mi][ni][2] * SC);
                const float p3 = exp2f(acc[mi][ni][3] * SC);
                const __half2 h0 = __floats2half2_rn(p0, p1);
                const __half2 h1 = __floats2half2_rn(p2, p3);
                *(__half2*)(Ch + row * ldc + col)       = h0;
                *(__half2*)(Ch + (row + 8) * ldc + col) = h1;
                // sum the rounded values so numerator/denominator stay consistent
                const float2 f0 = __half22float2(h0);
                const float2 f1 = __half22float2(h1);
                rs[mi * 2 + 0] += f0.x + f0.y;
                rs[mi * 2 + 1] += f1.x + f1.y;
            }
        }
        #pragma unroll
        for (int i = 0; i < 4; i++) {
            rs[i] += __shfl_xor_sync(0xffffffffu, rs[i], 1);
            rs[i] += __shfl_xor_sync(0xffffffffu, rs[i], 2);
        }
        if ((lane & 3) == 0) {
            #pragma unroll
            for (int mi = 0; mi < 2; ++mi) {
                const long row = mBase + wm + mi * 16 + qr;
                atomicAdd(&g_rowsum[row],     rs[mi * 2 + 0]);
                atomicAdd(&g_rowsum[row + 8], rs[mi * 2 + 1]);
            }
        }
    } else {
        #pragma unroll
        for (int mi = 0; mi < 2; ++mi) {
            const long row  = mBase + wm + mi * 16 + qr;
            const float inv0 = 1.0f / g_rowsum[row];
            const float inv1 = 1.0f / g_rowsum[row + 8];
            #pragma unroll
            for (int ni = 0; ni < 8; ++ni) {
                const long col = nBase + wn + ni * 8 + qc;
                const float2 o0 = make_float2(acc[mi][ni][0] * inv0,
                                              acc[mi][ni][1] * inv0);
                const float2 o1 = make_float2(acc[mi][ni][2] * inv1,
                                              acc[mi][ni][3] * inv1);
                *(float2*)(Cf + row * ldc + col)       = o0;
                *(float2*)(Cf + (row + 8) * ldc + col) = o1;
            }
        }
    }
}

// ---------------- prep kernels ----------------
// x fp32 -> fp16, and zero the rowsum accumulators
__global__ void k_cvt_x(const float* __restrict__ x) {
    const long g = (long)blockIdx.x * blockDim.x + threadIdx.x;
    const long i = g * 4;
    const float4 v = *(const float4*)(x + i);
    *(__half2*)(g_xh + i)     = __floats2half2_rn(v.x, v.y);
    *(__half2*)(g_xh + i + 2) = __floats2half2_rn(v.z, v.w);
    if (g < NTOK) g_rowsum[g] = 0.f;
}

// straight fp32->fp16 convert of Wq (z=0) and Wk (z=1), layout preserved [din][dout]
__global__ void k_cvt_wqk(const float* __restrict__ Wq,
                          const float* __restrict__ Wk) {
    const float* W = (blockIdx.z == 0) ? Wq : Wk;
    __half* O = (blockIdx.z == 0) ? g_wq : g_wk;
    const long i = ((long)blockIdx.x * blockDim.x + threadIdx.x) * 4;
    const float4 v = *(const float4*)(W + i);
    *(__half2*)(O + i)     = __floats2half2_rn(v.x, v.y);
    *(__half2*)(O + i + 2) = __floats2half2_rn(v.z, v.w);
}

// Wv [din][dout] fp32 -> g_wvt [dout][din] fp16 (transpose + convert)
__global__ void k_cvt_wvT(const float* __restrict__ Wv) {
    __shared__ float t[32][33];
    const int x0 = blockIdx.x * 32, y0 = blockIdx.y * 32;
    for (int r = threadIdx.y; r < 32; r += 8)
        t[r][threadIdx.x] = Wv[(long)(y0 + r) * DIM + x0 + threadIdx.x];
    __syncthreads();
    for (int r = threadIdx.y; r < 32; r += 8)
        g_wvt[(long)(x0 + r) * DIM + y0 + threadIdx.x] =
            __float2half_rn(t[threadIdx.x][r]);
}

// ---------------- GEMM entry points ----------------
// QK fold: scores = x Wq Wk^T x^T.
// g_mt[d][i] = sum_j g_wk[d][j]*g_wq[i][j]  (contraction over dout j; both
//              stored [din][dout] K-contiguous) = (Wk Wq^T)[d][i]
// Q'[n][d]   = sum_i x[n][i]*g_mt[d][i] = (x Wq Wk^T)[n][d]
// scores[n][m] = sum_d Q'[n][d]*x[m][d] = q_n . k_m exactly.
__global__ void k_gemm_mt()  { gemm_core<0>(g_wk, g_wq, g_mt, nullptr, DIM, DIM); }
__global__ void k_gemm_qp()  { gemm_core<0>(g_xh, g_mt, g_qp, nullptr, DIM, DIM); }
// V^T[d][n] = sum_i Wv^T[d][i]*x[n][i]  -> fused projection+transpose
__global__ void k_gemm_vt()  { gemm_core<0>(g_wvt, g_xh, g_vt, nullptr, DIM, NTOK); }
// scores + softmax numerator (K operand is x itself)
__global__ void k_gemm_s()   { gemm_core<1>(g_qp, g_xh, g_p, nullptr, DIM, NTOK); }
// out = P @ V, normalized
__global__ void k_gemm_o(float* __restrict__ out) {
    gemm_core<2>(g_p, g_vt, nullptr, out, NTOK, DIM);
}

// ---------------- launch ----------------
extern "C" void kernel_launch(void* const* d_in, const int* in_sizes, int n_in,
                              void* d_out, int out_size) {
    const float* x  = (const float*)d_in[0];
    const float* Wq = (const float*)d_in[1];
    const float* Wk = (const float*)d_in[2];
    const float* Wv = (const float*)d_in[3];
    float* out = (float*)d_out;

    k_cvt_x<<<(NTOK * DIM) / (256 * 4), 256>>>(x);
    k_cvt_wqk<<<dim3((DIM * DIM) / (256 * 4), 1, 2), 256>>>(Wq, Wk);
    k_cvt_wvT<<<dim3(32, 32), dim3(32, 8)>>>(Wv);
    k_gemm_mt<<<dim3(DIM / 128, DIM / 128), 256>>>();
    k_gemm_qp<<<dim3(DIM / 128, NTOK / 128), 256>>>();
    k_gemm_vt<<<dim3(NTOK / 128, DIM / 128), 256>>>();
    k_gemm_s<<<dim3(NTOK / 128, NTOK / 128), 256>>>();
    k_gemm_o<<<dim3(DIM / 128, NTOK / 128), 256>>>(out);
}

// round 12
// speedup vs baseline: 1.0625x; 1.0185x over previous
#include <cuda_runtime.h>
#include <cuda_fp16.h>
#include <cstdint>

#define NTOK 8192
#define DIM  1024

// ---------------- static device scratch (no runtime allocation) ----------------
__device__ __half g_xh[NTOK * DIM];             // x fp16 (also serves as K operand)
__device__ __half g_wq[DIM * DIM];              // Wq fp16 [din][dout]
__device__ __half g_wk[DIM * DIM];              // Wk fp16 [din][dout]
__device__ __half g_wvt[DIM * DIM];             // Wv^T fp16 [dout][din]
__device__ __half g_mt[DIM * DIM];              // g_mt[d][i] = sum_j Wk[d][j] Wq[i][j]
__device__ __half g_qp[NTOK * DIM];             // Q' = x @ (Wq Wk^T): [n][d]
__device__ __half g_vt[DIM * NTOK];             // V^T: [d][n]
__device__ __half g_p[(size_t)NTOK * NTOK];     // unnormalized softmax numerator
__device__ float  g_rowsum[NTOK];               // softmax denominators

// ---------------- helpers ----------------
__device__ __forceinline__ unsigned sptr(const void* p) {
    return (unsigned)__cvta_generic_to_shared(p);
}
__device__ __forceinline__ void cp16(void* dst, const void* src) {
    asm volatile("cp.async.cg.shared.global [%0], [%1], 16;\n"
                 :: "r"(sptr(dst)), "l"(src));
}

// ---------------- shared GEMM core: C[M,N] = A[M,K] @ B[N,K]^T ----------------
// (verbatim from the passing R2/R8 kernels)
// A, B fp16 row-major (K contiguous). CTA tile 128x128, K-step 32, 8 warps (4x2),
// warp tile 32x64, mma.sync.m16n8k16 with fp32 accumulation.
// Smem rows padded to 40 halves (80B stride -> 20-bank stride: 8-row LDSM groups
// hit banks {0,20,8,28,16,4,24,12}(+0..3) = all 32 banks -> conflict-free).
//
// EPI 0: store fp16 C
// EPI 1: P = exp2(C*scale*log2e) fp16 + atomic fp32 row sums
// EPI 2: C * (1/rowsum[row]) -> fp32 out
template<int EPI>
__device__ __forceinline__ void gemm_core(const __half* __restrict__ A,
                                          const __half* __restrict__ B,
                                          __half* __restrict__ Ch,
                                          float* __restrict__ Cf,
                                          int K, int ldc)
{
    __shared__ __half sA[2][128 * 40];
    __shared__ __half sB[2][128 * 40];

    const int tid  = threadIdx.x;
    const int lane = tid & 31;
    const int warp = tid >> 5;
    const int wm   = (warp & 3) * 32;
    const int wn   = (warp >> 2) * 64;

    const long mBase = (long)blockIdx.y * 128;
    const long nBase = (long)blockIdx.x * 128;
    const __half* Ag = A + mBase * K;
    const __half* Bg = B + nBase * K;

    // loader mapping: 512 16B-chunks per tile, 2 per thread (rows r0, r0+64)
    const int r0 = tid >> 2;
    const int c8 = (tid & 3) * 8;

    float acc[2][8][4];
    #pragma unroll
    for (int i = 0; i < 2; i++)
        #pragma unroll
        for (int j = 0; j < 8; j++)
            #pragma unroll
            for (int q = 0; q < 4; q++) acc[i][j][q] = 0.f;

    const int KT = K >> 5;

    // prologue: stage 0
    {
        cp16(&sA[0][r0 * 40 + c8],        Ag + (long)r0 * K + c8);
        cp16(&sA[0][(r0 + 64) * 40 + c8], Ag + (long)(r0 + 64) * K + c8);
        cp16(&sB[0][r0 * 40 + c8],        Bg + (long)r0 * K + c8);
        cp16(&sB[0][(r0 + 64) * 40 + c8], Bg + (long)(r0 + 64) * K + c8);
        asm volatile("cp.async.commit_group;\n");
    }

    int buf = 0;
    for (int kt = 0; kt < KT; ++kt) {
        if (kt + 1 < KT) {
            const int nb = buf ^ 1;
            const long ko = (long)(kt + 1) * 32 + c8;
            cp16(&sA[nb][r0 * 40 + c8],        Ag + (long)r0 * K + ko);
            cp16(&sA[nb][(r0 + 64) * 40 + c8], Ag + (long)(r0 + 64) * K + ko);
            cp16(&sB[nb][r0 * 40 + c8],        Bg + (long)r0 * K + ko);
            cp16(&sB[nb][(r0 + 64) * 40 + c8], Bg + (long)(r0 + 64) * K + ko);
            asm volatile("cp.async.commit_group;\n");
            asm volatile("cp.async.wait_group 1;\n");
        } else {
            asm volatile("cp.async.wait_group 0;\n");
        }
        __syncthreads();

        const __half* a_s = sA[buf];
        const __half* b_s = sB[buf];
        #pragma unroll
        for (int kk = 0; kk < 2; ++kk) {
            unsigned af[2][4];
            unsigned bf[4][4];
            #pragma unroll
            for (int mi = 0; mi < 2; ++mi) {
                const int row = wm + mi * 16 + (lane & 15);
                const int col = kk * 16 + (lane >> 4) * 8;
                const unsigned addr = sptr(a_s + row * 40 + col);
                asm volatile("ldmatrix.sync.aligned.m8n8.x4.shared.b16 {%0,%1,%2,%3}, [%4];\n"
                             : "=r"(af[mi][0]), "=r"(af[mi][1]),
                               "=r"(af[mi][2]), "=r"(af[mi][3])
                             : "r"(addr));
            }
            #pragma unroll
            for (int nq = 0; nq < 4; ++nq) {
                const int g   = lane >> 3;
                const int row = wn + nq * 16 + (g >> 1) * 8 + (lane & 7);
                const int col = kk * 16 + (g & 1) * 8;
                const unsigned addr = sptr(b_s + row * 40 + col);
                asm volatile("ldmatrix.sync.aligned.m8n8.x4.shared.b16 {%0,%1,%2,%3}, [%4];\n"
                             : "=r"(bf[nq][0]), "=r"(bf[nq][1]),
                               "=r"(bf[nq][2]), "=r"(bf[nq][3])
                             : "r"(addr));
            }
            #pragma unroll
            for (int mi = 0; mi < 2; ++mi) {
                #pragma unroll
                for (int ni = 0; ni < 8; ++ni) {
                    const unsigned b0 = bf[ni >> 1][(ni & 1) * 2 + 0];
                    const unsigned b1 = bf[ni >> 1][(ni & 1) * 2 + 1];
                    asm volatile(
                        "mma.sync.aligned.m16n8k16.row.col.f32.f16.f16.f32 "
                        "{%0,%1,%2,%3},{%4,%5,%6,%7},{%8,%9},{%0,%1,%2,%3};\n"
                        : "+f"(acc[mi][ni][0]), "+f"(acc[mi][ni][1]),
                          "+f"(acc[mi][ni][2]), "+f"(acc[mi][ni][3])
                        : "r"(af[mi][0]), "r"(af[mi][1]),
                          "r"(af[mi][2]), "r"(af[mi][3]),
                          "r"(b0), "r"(b1));
                }
            }
        }
        __syncthreads();
        buf ^= 1;
    }

    // ---------------- epilogue ----------------
    const int qr = lane >> 2;
    const int qc = (lane & 3) * 2;

    if (EPI == 0) {
        #pragma unroll
        for (int mi = 0; mi < 2; ++mi) {
            const long row = mBase + wm + mi * 16 + qr;
            #pragma unroll
            for (int ni = 0; ni < 8; ++ni) {
                const long col = nBase + wn + ni * 8 + qc;
                *(__half2*)(Ch + row * ldc + col) =
                    __floats2half2_rn(acc[mi][ni][0], acc[mi][ni][1]);
                *(__half2*)(Ch + (row + 8) * ldc + col) =
                    __floats2half2_rn(acc[mi][ni][2], acc[mi][ni][3]);
            }
        }
    } else if (EPI == 1) {
        // exp(s / sqrt(1024)) = exp2(s * 0.03125 * log2(e)); |s*scale| <~ 3 so
        // no max subtraction needed (softmax is shift invariant, range is safe).
        const float SC = 0.03125f * 1.4426950408889634f;
        float rs[4] = {0.f, 0.f, 0.f, 0.f};
        #pragma unroll
        for (int mi = 0; mi < 2; ++mi) {
            const long row = mBase + wm + mi * 16 + qr;
            #pragma unroll
            for (int ni = 0; ni < 8; ++ni) {
                const long col = nBase + wn + ni * 8 + qc;
                const float p0 = exp2f(acc[mi][ni][0] * SC);
                const float p1 = exp2f(acc[mi][ni][1] * SC);
                const float p2 = exp2f(acc[mi][ni][2] * SC);
                const float p3 = exp2f(acc[mi][ni][3] * SC);
                const __half2 h0 = __floats2half2_rn(p0, p1);
                const __half2 h1 = __floats2half2_rn(p2, p3);
                *(__half2*)(Ch + row * ldc + col)       = h0;
                *(__half2*)(Ch + (row + 8) * ldc + col) = h1;
                // sum the rounded values so numerator/denominator stay consistent
                const float2 f0 = __half22float2(h0);
                const float2 f1 = __half22float2(h1);
                rs[mi * 2 + 0] += f0.x + f0.y;
                rs[mi * 2 + 1] += f1.x + f1.y;
            }
        }
        #pragma unroll
        for (int i = 0; i < 4; i++) {
            rs[i] += __shfl_xor_sync(0xffffffffu, rs[i], 1);
            rs[i] += __shfl_xor_sync(0xffffffffu, rs[i], 2);
        }
        if ((lane & 3) == 0) {
            #pragma unroll
            for (int mi = 0; mi < 2; ++mi) {
                const long row = mBase + wm + mi * 16 + qr;
                atomicAdd(&g_rowsum[row],     rs[mi * 2 + 0]);
                atomicAdd(&g_rowsum[row + 8], rs[mi * 2 + 1]);
            }
        }
    } else {
        #pragma unroll
        for (int mi = 0; mi < 2; ++mi) {
            const long row  = mBase + wm + mi * 16 + qr;
            const float inv0 = 1.0f / g_rowsum[row];
            const float inv1 = 1.0f / g_rowsum[row + 8];
            #pragma unroll
            for (int ni = 0; ni < 8; ++ni) {
                const long col = nBase + wn + ni * 8 + qc;
                const float2 o0 = make_float2(acc[mi][ni][0] * inv0,
                                              acc[mi][ni][1] * inv0);
                const float2 o1 = make_float2(acc[mi][ni][2] * inv1,
                                              acc[mi][ni][3] * inv1);
                *(float2*)(Cf + row * ldc + col)       = o0;
                *(float2*)(Cf + (row + 8) * ldc + col) = o1;
            }
        }
    }
}

// ---------------- prep kernels ----------------
// x fp32 -> fp16, and zero the rowsum accumulators
__global__ void k_cvt_x(const float* __restrict__ x) {
    const long g = (long)blockIdx.x * blockDim.x + threadIdx.x;
    const long i = g * 4;
    const float4 v = *(const float4*)(x + i);
    *(__half2*)(g_xh + i)     = __floats2half2_rn(v.x, v.y);
    *(__half2*)(g_xh + i + 2) = __floats2half2_rn(v.z, v.w);
    if (g < NTOK) g_rowsum[g] = 0.f;
}

// straight fp32->fp16 convert of Wq (z=0) and Wk (z=1), layout preserved [din][dout]
__global__ void k_cvt_wqk(const float* __restrict__ Wq,
                          const float* __restrict__ Wk) {
    const float* W = (blockIdx.z == 0) ? Wq : Wk;
    __half* O = (blockIdx.z == 0) ? g_wq : g_wk;
    const long i = ((long)blockIdx.x * blockDim.x + threadIdx.x) * 4;
    const float4 v = *(const float4*)(W + i);
    *(__half2*)(O + i)     = __floats2half2_rn(v.x, v.y);
    *(__half2*)(O + i + 2) = __floats2half2_rn(v.z, v.w);
}

// Wv [din][dout] fp32 -> g_wvt [dout][din] fp16 (transpose + convert)
__global__ void k_cvt_wvT(const float* __restrict__ Wv) {
    __shared__ float t[32][33];
    const int x0 = blockIdx.x * 32, y0 = blockIdx.y * 32;
    for (int r = threadIdx.y; r < 32; r += 8)
        t[r][threadIdx.x] = Wv[(long)(y0 + r) * DIM + x0 + threadIdx.x];
    __syncthreads();
    for (int r = threadIdx.y; r < 32; r += 8)
        g_wvt[(long)(x0 + r) * DIM + y0 + threadIdx.x] =
            __float2half_rn(t[threadIdx.x][r]);
}

// ---------------- GEMM entry points ----------------
// QK fold: scores = x Wq Wk^T x^T.
// g_mt[d][i] = sum_j g_wk[d][j]*g_wq[i][j]  (contraction over dout j; both
//              stored [din][dout] K-contiguous) = (Wk Wq^T)[d][i]
// Q'[n][d]   = sum_i x[n][i]*g_mt[d][i] = (x Wq Wk^T)[n][d]
// scores[n][m] = sum_d Q'[n][d]*x[m][d] = q_n . k_m exactly.
//
// mt (64 CTAs, latency-bound alone: measured 23.7us at occ 12%) is packed into
// the same launch as vt (512 CTAs): z=0 -> vt, z=1 & x<8 -> mt. 576 equal-work
// CTAs fit the same 2 waves vt needs alone, so mt rides along for free.
__global__ void __launch_bounds__(256, 2) k_gemm_mtvt() {
    if (blockIdx.z == 0) {
        // V^T[d][n] = sum_i Wv^T[d][i]*x[n][i]  (fused projection+transpose)
        gemm_core<0>(g_wvt, g_xh, g_vt, nullptr, DIM, NTOK);
    } else {
        if (blockIdx.x >= 8) return;     // mt is only 8x8 tiles
        gemm_core<0>(g_wk, g_wq, g_mt, nullptr, DIM, DIM);
    }
}
__global__ void __launch_bounds__(256, 2) k_gemm_qp() {
    gemm_core<0>(g_xh, g_mt, g_qp, nullptr, DIM, DIM);
}
// scores + softmax numerator (K operand is x itself)
__global__ void __launch_bounds__(256, 2) k_gemm_s() {
    gemm_core<1>(g_qp, g_xh, g_p, nullptr, DIM, NTOK);
}
// out = P @ V, normalized
__global__ void __launch_bounds__(256, 2) k_gemm_o(float* __restrict__ out) {
    gemm_core<2>(g_p, g_vt, nullptr, out, NTOK, DIM);
}

// ---------------- launch ----------------
extern "C" void kernel_launch(void* const* d_in, const int* in_sizes, int n_in,
                              void* d_out, int out_size) {
    const float* x  = (const float*)d_in[0];
    const float* Wq = (const float*)d_in[1];
    const float* Wk = (const float*)d_in[2];
    const float* Wv = (const float*)d_in[3];
    float* out = (float*)d_out;

    k_cvt_x<<<(NTOK * DIM) / (256 * 4), 256>>>(x);
    k_cvt_wqk<<<dim3((DIM * DIM) / (256 * 4), 1, 2), 256>>>(Wq, Wk);
    k_cvt_wvT<<<dim3(32, 32), dim3(32, 8)>>>(Wv);
    k_gemm_mtvt<<<dim3(NTOK / 128, DIM / 128, 2), 256>>>();
    k_gemm_qp<<<dim3(DIM / 128, NTOK / 128), 256>>>();
    k_gemm_s<<<dim3(NTOK / 128, NTOK / 128), 256>>>();
    k_gemm_o<<<dim3(DIM / 128, NTOK / 128), 256>>>(out);
}